// round 15
// baseline (speedup 1.0000x reference)
#include <cuda_runtime.h>

// LocalActivationUnit: score[b,t] = relu([q,k,q-k,q*k] @ W0 + b0) @ W1 + b1
// Folded:  h = qA_b + k . C_b ; score = relu(h) @ W1 + b1.
//
// R13: 256 thr/CTA, 2 CTAs/SM -> 16 warps/SM. Balanced 8x8 microtile kept;
//      K split across lane bit 4 (kg): each thread does K/2=64 p-steps,
//      halves combined via shfl_xor(16) + f32x2 add. sA stride 130 with a
//      1-word gap between K-halves keeps scalar A-LDS conflict-free.

#define NB 1024
#define NT 200
#define NE 128
#define NH 64
#define CHUNK 128
#define SAS 130   // sA row stride: [p0..63][gap][p64..127]

__device__ __forceinline__ unsigned long long pack2(float x) {
    unsigned long long r;
    asm("mov.b64 %0, {%1, %1};" : "=l"(r) : "r"(__float_as_uint(x)));
    return r;
}
__device__ __forceinline__ void ffma2(unsigned long long &acc, unsigned long long a,
                                      unsigned long long b) {
    asm("fma.rn.f32x2 %0, %1, %2, %0;" : "+l"(acc) : "l"(a), "l"(b));
}
__device__ __forceinline__ void fadd2(unsigned long long &d, unsigned long long a,
                                      unsigned long long b) {
    asm("add.rn.f32x2 %0, %1, %2;" : "=l"(d) : "l"(a), "l"(b));
}
__device__ __forceinline__ float2 unpack2(unsigned long long v) {
    unsigned int lo, hi;
    asm("mov.b64 {%0, %1}, %2;" : "=r"(lo), "=r"(hi) : "l"(v));
    return make_float2(__uint_as_float(lo), __uint_as_float(hi));
}

__global__ void __launch_bounds__(256, 2)
lau_kernel(const float* __restrict__ query,
           const float* __restrict__ keys,
           const float* __restrict__ W0,
           const float* __restrict__ b0,
           const float* __restrict__ W1,
           const float* __restrict__ b1,
           float* __restrict__ out)
{
    extern __shared__ float smem[];
    float* sC  = smem;                 // [128][64] rows in permuted-p order
    float* sA  = smem + NE * NH;       // [CHUNK][SAS] keys, e-permuted, split halves
    float* sq  = sA + CHUNK * SAS;     // [128]
    float* sqA = sq + NE;              // [64]

    const int tid = threadIdx.x;
    const int b   = blockIdx.x;

    // ---- load q ----
    if (tid < NE) sq[tid] = query[b * NE + tid];
    __syncthreads();

    // ---- precompute C_b into smem (rows permuted: p -> e(p)=4*(p&31)+(p>>5)) ----
    const float* W0a = W0;
    const float* W0b = W0 + 128 * NH;
    const float* W0c = W0 + 256 * NH;
    const float* W0d = W0 + 384 * NH;
    #pragma unroll
    for (int j = 0; j < 8; j++) {
        int f = tid + 256 * j;          // float4 index, [0, 2048)
        int p = f >> 4;                 // 16 float4 per row
        int c = f & 15;
        int e = 4 * (p & 31) + (p >> 5);
        float qe = sq[e];
        float4 wb = *(const float4*)(W0b + e * NH + c * 4);
        float4 wc = *(const float4*)(W0c + e * NH + c * 4);
        float4 wd = *(const float4*)(W0d + e * NH + c * 4);
        float4 cv;
        cv.x = (wb.x - wc.x) + qe * wd.x;
        cv.y = (wb.y - wc.y) + qe * wd.y;
        cv.z = (wb.z - wc.z) + qe * wd.z;
        cv.w = (wb.w - wc.w) + qe * wd.w;
        *(float4*)&sC[f * 4] = cv;
    }
    // qA partials: 4 groups of 32 e-terms, scratch in sA
    {
        int h = tid & 63, g = tid >> 6;
        float ps = 0.f;
        int e0 = g * 32;
        #pragma unroll 4
        for (int e = e0; e < e0 + 32; e++)
            ps += sq[e] * (W0a[e * NH + h] + W0c[e * NH + h]);
        sA[g * 64 + h] = ps;
    }
    __syncthreads();
    if (tid < NH)
        sqA[tid] = b0[tid] + sA[tid] + sA[64 + tid] + sA[128 + tid] + sA[192 + tid];
    // (loop-start __syncthreads orders this vs. sA reuse)

    // ---- per-thread role ----
    const int w    = tid >> 5;          // warp 0..7
    const int lane = tid & 31;
    const int kg   = lane >> 4;         // K-half
    const int tyl  = (lane >> 3) & 1;   // row sub-group within warp
    const int tx   = lane & 7;          // col group
    const int ty   = w * 2 + tyl;       // 0..15 -> 8 rows each

    float w1v[8];
    *(float4*)&w1v[0] = *(const float4*)(W1 + tx * 4);
    *(float4*)&w1v[4] = *(const float4*)(W1 + 32 + tx * 4);
    const float b1v = b1[0];
    const float* bp  = sC + tx * 4;
    const float* bpk = bp + (kg * 64) * NH;

    // ---- main loop over T in 128-row chunks ----
    for (int t0 = 0; t0 < NT; t0 += CHUNK) {
        const int rows = min(CHUNK, NT - t0);
        __syncthreads();   // previous GEMM done reading sA

        // loader: warp per row; lane c4 scatters its float4 (e-permuted) to
        // words {c4, 32+c4, 65+c4, 97+c4} (banks = c4+const: conflict-free)
        for (int f = tid; f < rows * 32; f += 256) {
            int row = f >> 5, c4 = f & 31;
            float4 v = *(const float4*)(keys + ((long)b * NT + t0 + row) * NE + c4 * 4);
            float* base = sA + row * SAS + c4;
            base[0]  = v.x;   // p = c4
            base[32] = v.y;   // p = 32+c4
            base[65] = v.z;   // p = 64+c4
            base[97] = v.w;   // p = 96+c4
        }
        __syncthreads();

        if (w * 16 < rows) {   // warp-uniform tail guard
            // GEMM: acc[8 rows][4 col-pairs] over this thread's K half
            unsigned long long acc[8][4];
            #pragma unroll
            for (int r = 0; r < 8; r++)
                #pragma unroll
                for (int c = 0; c < 4; c++) acc[r][c] = 0ull;

            const float* ap = sA + (ty * 8) * SAS + kg * 65;
            #pragma unroll 4
            for (int pp = 0; pp < 64; pp++) {
                const float* be = bpk + pp * NH;
                ulonglong2 blo = *(const ulonglong2*)be;        // cols tx*4..+3
                ulonglong2 bhi = *(const ulonglong2*)(be + 32); // cols 32+tx*4..+3
                #pragma unroll
                for (int r = 0; r < 8; r++) {
                    unsigned long long aa = pack2(ap[r * SAS + pp]);
                    ffma2(acc[r][0], aa, blo.x);
                    ffma2(acc[r][1], aa, blo.y);
                    ffma2(acc[r][2], aa, bhi.x);
                    ffma2(acc[r][3], aa, bhi.y);
                }
            }

            // combine K halves: partner lane = lane ^ 16 (same ty/tx, other kg)
            #pragma unroll
            for (int r = 0; r < 8; r++)
                #pragma unroll
                for (int c = 0; c < 4; c++) {
                    unsigned long long o =
                        __shfl_xor_sync(0xffffffffu, acc[r][c], 16);
                    fadd2(acc[r][c], acc[r][c], o);
                }

            // epilogue (row-split across kg): relu(acc+qA).W1, 8-lane reduce
            #pragma unroll
            for (int r = 0; r < 4; r++) {
                const int ridx = kg * 4 + r;
                const int trow = ty * 8 + ridx;
                float s = 0.f;
                #pragma unroll
                for (int cp = 0; cp < 4; cp++) {
                    float2 v = unpack2(acc[ridx][cp]);
                    int h = (cp < 2) ? (tx * 4 + cp * 2) : (32 + tx * 4 + (cp - 2) * 2);
                    float x0 = v.x + sqA[h];
                    float x1 = v.y + sqA[h + 1];
                    x0 = x0 > 0.f ? x0 : 0.f;
                    x1 = x1 > 0.f ? x1 : 0.f;
                    s += x0 * w1v[cp * 2] + x1 * w1v[cp * 2 + 1];
                }
                s += __shfl_down_sync(0xffffffffu, s, 4);
                s += __shfl_down_sync(0xffffffffu, s, 2);
                s += __shfl_down_sync(0xffffffffu, s, 1);
                if (tx == 0 && trow < rows)
                    out[b * NT + t0 + trow] = s + b1v;
            }
        }
    }
}

extern "C" void kernel_launch(void* const* d_in, const int* in_sizes, int n_in,
                              void* d_out, int out_size)
{
    const float* query = (const float*)d_in[0];
    const float* keys  = (const float*)d_in[1];
    const float* W0    = (const float*)d_in[2];
    const float* b0    = (const float*)d_in[3];
    const float* W1    = (const float*)d_in[4];
    const float* b1    = (const float*)d_in[5];
    float* out = (float*)d_out;

    const int smem_bytes = (NE * NH + CHUNK * SAS + NE + NH) * (int)sizeof(float);
    cudaFuncSetAttribute(lau_kernel, cudaFuncAttributeMaxDynamicSharedMemorySize,
                         smem_bytes);
    lau_kernel<<<NB, 256, smem_bytes>>>(query, keys, W0, b0, W1, b1, out);
}